// round 12
// baseline (speedup 1.0000x reference)
#include <cuda_runtime.h>
#include <cuda_bf16.h>
#include <stdint.h>

#define E       64
#define BLOCK   256
#define ITEMS   16
#define CHUNK   (BLOCK * ITEMS)   // 4096
#define HSTRIDE 264               // u16 per expert row: 16B-aligned, bank-decorrelating

// Scratch (no allocation allowed): supports up to B = 4096 blocks.
__device__ uint32_t g_counts[E * 4096];
__device__ uint32_t g_totals[E];   // zero-initialized; re-zeroed by k_scatter b==0

__device__ __forceinline__ uint32_t warp_incl_scan(uint32_t x, int lane) {
#pragma unroll
    for (int o = 1; o < 32; o <<= 1) {
        uint32_t y = __shfl_up_sync(0xffffffffu, x, o);
        if (lane >= o) x += y;
    }
    return x;
}

// ---------------------------------------------------------------------------
// K1: per-(expert, block) histogram, expert-major: g_counts[e*B + b].
// Per-warp sub-histograms: same-expert atomics never contend across warps.
// ---------------------------------------------------------------------------
__global__ __launch_bounds__(BLOCK) void k_hist(const int* __restrict__ experts, int B) {
    __shared__ uint32_t h[8][E];
    const int t = threadIdx.x;
    const int b = blockIdx.x;
    const int warp = t >> 5;

    ((uint32_t*)h)[t] = 0u;
    ((uint32_t*)h)[t + BLOCK] = 0u;
    __syncthreads();

    const int4* p = (const int4*)(experts + (size_t)b * CHUNK);
#pragma unroll
    for (int i = 0; i < CHUNK / (4 * BLOCK); i++) {     // 4 iterations
        int4 x = p[i * BLOCK + t];
        atomicAdd(&h[warp][x.x], 1u);
        atomicAdd(&h[warp][x.y], 1u);
        atomicAdd(&h[warp][x.z], 1u);
        atomicAdd(&h[warp][x.w], 1u);
    }
    __syncthreads();

    if (t < E) {
        uint32_t c = 0;
#pragma unroll
        for (int w = 0; w < 8; w++) c += h[w][t];
        g_counts[(size_t)t * B + b] = c;
        atomicAdd(&g_totals[t], c);
    }
}

// ---------------------------------------------------------------------------
// K2: one block per expert. Seeds with exclusive scan of expert totals, then
// scans this expert's B per-block counts in place -> global start offsets.
// Also writes num_tokens_per_expert (float).
// ---------------------------------------------------------------------------
__global__ __launch_bounds__(256) void k_scan(int B, float* __restrict__ out_counts) {
    __shared__ uint32_t s_wsum[8];
    __shared__ uint32_t s_base;

    const int e = blockIdx.x;
    const int t = threadIdx.x;
    const int lane = t & 31, warp = t >> 5;

    if (t < 32) {
        uint32_t a = g_totals[t];
        uint32_t c = g_totals[t + 32];
        uint32_t contrib = (t < e ? a : 0u) + ((t + 32) < e ? c : 0u);
#pragma unroll
        for (int o = 16; o > 0; o >>= 1)
            contrib += __shfl_down_sync(0xffffffffu, contrib, o);
        if (t == 0) s_base = contrib;
    }
    if (t == 0) out_counts[e] = (float)g_totals[e];

    uint32_t* row = g_counts + (size_t)e * B;
    const int VB = B >> 8;               // 8 for B=2048
    uint32_t run = 0;
    uint32_t el[16];
#pragma unroll 8
    for (int k = 0; k < VB; k++) {
        uint32_t v = row[t * VB + k];
        el[k] = run;
        run += v;
    }

    uint32_t inc = warp_incl_scan(run, lane);
    if (lane == 31) s_wsum[warp] = inc;
    __syncthreads();
    if (t == 0) {
        uint32_t acc = 0;
#pragma unroll
        for (int w = 0; w < 8; w++) { uint32_t x = s_wsum[w]; s_wsum[w] = acc; acc += x; }
    }
    __syncthreads();

    uint32_t excl = inc - run + s_wsum[warp] + s_base;
#pragma unroll 8
    for (int k = 0; k < VB; k++)
        row[t * VB + k] = el[k] + excl;
}

// ---------------------------------------------------------------------------
// K3: stable scatter. Block radix-rank (padded hist rows) + smem overlay.
// Expert ids byte-packed; ranks via SIMD byte-compare -> low register count.
// ---------------------------------------------------------------------------
__global__ __launch_bounds__(BLOCK, 5) void k_scatter(
    const float* __restrict__ scores,
    const int*   __restrict__ experts,
    float* __restrict__ out_scores,
    float* __restrict__ out_idx,
    int B)
{
    __shared__ uint32_t s_buf[(E * HSTRIDE) / 2];   // 33,792 B overlay
    __shared__ int      s_delta[E];
    __shared__ uint32_t s_lbase[E];

    uint16_t* hist   = (uint16_t*)s_buf;    // [E][HSTRIDE] counts -> excl prefix
    float*    s_val  = (float*)s_buf;       // words [0, CHUNK)
    uint32_t* s_meta = s_buf + CHUNK;       // words [CHUNK, 2*CHUNK)

    const int t = threadIdx.x;
    const int b = blockIdx.x;
    const int lane = t & 31, warp = t >> 5;

    // Reset g_totals for the next replay (k_scan already consumed it; launches
    // in the captured graph serialize, so this is race-free and deterministic).
    if (b == 0 && t < E) g_totals[t] = 0u;

    // Byte-pack 16 expert ids (4 x LDG.128, coalesced).
    uint32_t epk[4];
    {
        const int4* ep = (const int4*)(experts + (size_t)b * CHUNK + t * ITEMS);
#pragma unroll
        for (int v = 0; v < 4; v++) {
            int4 x = ep[v];
            epk[v] = (uint32_t)x.x | ((uint32_t)x.y << 8) |
                     ((uint32_t)x.z << 16) | ((uint32_t)x.w << 24);
        }
    }

    // Zero hist: 8448 u32 words = 2112 uint4.
    uint4 z4 = make_uint4(0u, 0u, 0u, 0u);
#pragma unroll
    for (int i = 0; i < 8; i++) ((uint4*)s_buf)[i * BLOCK + t] = z4;
    if (t < 64) ((uint4*)s_buf)[8 * BLOCK + t] = z4;
    __syncthreads();

    // In-thread stable rank via SIMD byte compare; nibble-packed ranks.
    uint32_t rn0 = 0, rn1 = 0;
#pragma unroll
    for (int i = 0; i < ITEMS; i++) {
        uint32_t w  = epk[i >> 2];
        uint32_t ei = (w >> (8 * (i & 3))) & 0xFFu;
        uint32_t bc = ei * 0x01010101u;
        uint32_t r  = 0;
#pragma unroll
        for (int q = 0; q < 4; q++)
            if (q < (i >> 2)) r += __popc(__vcmpeq4(epk[q], bc));
        uint32_t pm = (1u << (8 * (i & 3))) - 1u;     // bytes j < i within word
        r += __popc(__vcmpeq4(w, bc) & pm);
        r >>= 3;                                       // 8 bits per byte-match
        if (i < 8) rn0 |= r << (4 * i);
        else       rn1 |= r << (4 * (i - 8));
        hist[ei * HSTRIDE + t] = (uint16_t)(r + 1);
    }
    __syncthreads();

    // Per-expert exclusive scan over 256 thread counts (8 experts/warp).
#pragma unroll
    for (int s = 0; s < E / 8; s++) {
        int ex = warp * (E / 8) + s;
        uint4 v = ((const uint4*)(hist + ex * HSTRIDE))[lane];   // 8 u16
        uint32_t w[4] = { v.x, v.y, v.z, v.w };
        uint32_t run = 0, el[8];
#pragma unroll
        for (int k = 0; k < 8; k++) {
            uint32_t c = (w[k >> 1] >> ((k & 1) * 16)) & 0xFFFFu;
            el[k] = run; run += c;
        }
        uint32_t inc = warp_incl_scan(run, lane);
        uint32_t excl = inc - run;
#pragma unroll
        for (int k = 0; k < 8; k++) el[k] += excl;
        uint4 o;
        o.x = el[0] | (el[1] << 16);
        o.y = el[2] | (el[3] << 16);
        o.z = el[4] | (el[5] << 16);
        o.w = el[6] | (el[7] << 16);
        ((uint4*)(hist + ex * HSTRIDE))[lane] = o;
        if (lane == 31) s_lbase[ex] = inc;   // row total (temp)
    }
    __syncthreads();

    // Warp 0: block-local expert bases + delta vs scanned global offsets.
    if (warp == 0) {
        uint32_t t0 = s_lbase[lane];
        uint32_t t1 = s_lbase[lane + 32];
        uint32_t i0 = warp_incl_scan(t0, lane);
        uint32_t tot0 = __shfl_sync(0xffffffffu, i0, 31);
        uint32_t e0 = i0 - t0;
        uint32_t i1 = warp_incl_scan(t1, lane);
        uint32_t e1 = i1 - t1 + tot0;
        uint32_t gb0 = g_counts[(size_t)lane * B + b];
        uint32_t gb1 = g_counts[(size_t)(lane + 32) * B + b];
        s_lbase[lane]       = e0;
        s_lbase[lane + 32]  = e1;
        s_delta[lane]       = (int)gb0 - (int)e0;
        s_delta[lane + 32]  = (int)gb1 - (int)e1;
    }
    __syncthreads();

    // Per-item local positions into registers (u16-packed).
    uint32_t p16[ITEMS / 2];
#pragma unroll
    for (int i = 0; i < ITEMS; i++) {
        uint32_t ei = (epk[i >> 2] >> (8 * (i & 3))) & 0xFFu;
        uint32_t r  = (i < 8) ? ((rn0 >> (4 * i)) & 0xFu)
                              : ((rn1 >> (4 * (i - 8))) & 0xFu);
        uint32_t p = s_lbase[ei] + (uint32_t)hist[ei * HSTRIDE + t] + r;
        if (i & 1) p16[i >> 1] |= p << 16;
        else       p16[i >> 1]  = p;
    }
    __syncthreads();   // all hist reads done -> safe to overlay

    // Stage scores + packed meta into sorted order (scores loaded coalesced).
    {
        const float4* sp = (const float4*)(scores + (size_t)b * CHUNK + t * ITEMS);
#pragma unroll
        for (int v = 0; v < 4; v++) {
            float4 x = sp[v];
            float vv[4] = { x.x, x.y, x.z, x.w };
#pragma unroll
            for (int j = 0; j < 4; j++) {
                int i = 4 * v + j;
                uint32_t ei = (epk[v] >> (8 * j)) & 0xFFu;
                uint32_t p  = (p16[i >> 1] >> ((i & 1) * 16)) & 0xFFFFu;
                s_val[p]  = vv[j];
                s_meta[p] = (uint32_t)(t * ITEMS + i) | (ei << 12);
            }
        }
    }
    __syncthreads();

    // Coalesced emit.
    const int chunk_base = b * CHUNK;
#pragma unroll
    for (int i = 0; i < ITEMS; i++) {
        int p = t + i * BLOCK;
        float v = s_val[p];
        uint32_t m = s_meta[p];
        int li = (int)(m & 0xFFFu);
        int ei = (int)(m >> 12);
        int gp = p + s_delta[ei];
        out_scores[gp] = v;
        out_idx[gp]    = (float)(chunk_base + li);
    }
}

// ---------------------------------------------------------------------------
extern "C" void kernel_launch(void* const* d_in, const int* in_sizes, int n_in,
                              void* d_out, int out_size) {
    const float* scores  = (const float*)d_in[0];
    const int*   experts = (const int*)d_in[1];
    const int N = in_sizes[0];            // 8,388,608
    const int B = N / CHUNK;              // 2048

    float* out        = (float*)d_out;
    float* out_scores = out;
    float* out_idx    = out + N;
    float* out_counts = out + 2 * (size_t)N;

    k_hist<<<B, BLOCK>>>(experts, B);
    k_scan<<<E, 256>>>(B, out_counts);
    k_scatter<<<B, BLOCK>>>(scores, experts, out_scores, out_idx, B);
}

// round 13
// speedup vs baseline: 1.0190x; 1.0190x over previous
#include <cuda_runtime.h>
#include <cuda_bf16.h>
#include <stdint.h>

#define E       64
#define BLOCK   256
#define ITEMS   16
#define CHUNK   (BLOCK * ITEMS)   // 4096

// Scratch (no allocation allowed): supports up to B = 4096 blocks.
__device__ uint32_t g_counts[E * 4096];
__device__ uint32_t g_totals[E];   // zero-initialized; re-zeroed by k_scatter b==0

__device__ __forceinline__ uint32_t warp_incl_scan(uint32_t x, int lane) {
#pragma unroll
    for (int o = 1; o < 32; o <<= 1) {
        uint32_t y = __shfl_up_sync(0xffffffffu, x, o);
        if (lane >= o) x += y;
    }
    return x;
}

// ---------------------------------------------------------------------------
// K1: per-(expert, block) histogram, expert-major: g_counts[e*B + b].
// Single shared hist (proven fastest). In-thread aggregation: atomic only at
// the LAST in-thread occurrence of each expert, adding its full count r+1.
// ---------------------------------------------------------------------------
__global__ __launch_bounds__(BLOCK) void k_hist(const int* __restrict__ experts, int B) {
    __shared__ uint32_t h[E];
    const int t = threadIdx.x;
    const int b = blockIdx.x;
    if (t < E) h[t] = 0u;
    __syncthreads();

    // Byte-pack 16 expert ids (4 x LDG.128, coalesced).
    uint32_t epk[4];
    {
        const int4* p = (const int4*)(experts + (size_t)b * CHUNK + t * ITEMS);
#pragma unroll
        for (int v = 0; v < 4; v++) {
            int4 x = p[v];
            epk[v] = (uint32_t)x.x | ((uint32_t)x.y << 8) |
                     ((uint32_t)x.z << 16) | ((uint32_t)x.w << 24);
        }
    }

#pragma unroll
    for (int i = 0; i < ITEMS; i++) {
        const int qw = i >> 2, k = i & 3;
        uint32_t w  = epk[qw];
        uint32_t ei = (w >> (8 * k)) & 0xFFu;
        uint32_t bc = ei * 0x01010101u;
        uint32_t eqw = __vcmpeq4(w, bc);
        uint32_t r = __popc(eqw & ((1u << (8 * k)) - 1u));          // before, in-word
        uint32_t a = (k < 3) ? __popc(eqw & (0xFFFFFFFFu << (8 * (k + 1)))) : 0u;
#pragma unroll
        for (int q = 0; q < 4; q++) {
            if (q < qw) r += __popc(__vcmpeq4(epk[q], bc));
            if (q > qw) a += __popc(__vcmpeq4(epk[q], bc));
        }
        if (a == 0u) atomicAdd(&h[ei], (r >> 3) + 1u);   // last occurrence
    }
    __syncthreads();

    if (t < E) {
        uint32_t c = h[t];
        g_counts[(size_t)t * B + b] = c;
        atomicAdd(&g_totals[t], c);
    }
}

// ---------------------------------------------------------------------------
// K2: one block per expert. Seeds with exclusive scan of expert totals, then
// scans this expert's B per-block counts in place -> global start offsets.
// Also writes num_tokens_per_expert (float).
// ---------------------------------------------------------------------------
__global__ __launch_bounds__(256) void k_scan(int B, float* __restrict__ out_counts) {
    __shared__ uint32_t s_wsum[8];
    __shared__ uint32_t s_base;

    const int e = blockIdx.x;
    const int t = threadIdx.x;
    const int lane = t & 31, warp = t >> 5;

    if (t < 32) {
        uint32_t a = g_totals[t];
        uint32_t c = g_totals[t + 32];
        uint32_t contrib = (t < e ? a : 0u) + ((t + 32) < e ? c : 0u);
#pragma unroll
        for (int o = 16; o > 0; o >>= 1)
            contrib += __shfl_down_sync(0xffffffffu, contrib, o);
        if (t == 0) s_base = contrib;
    }
    if (t == 0) out_counts[e] = (float)g_totals[e];

    uint32_t* row = g_counts + (size_t)e * B;
    const int VB = B >> 8;               // 8 for B=2048
    uint32_t run = 0;
    uint32_t el[16];
#pragma unroll 8
    for (int k = 0; k < VB; k++) {
        uint32_t v = row[t * VB + k];
        el[k] = run;
        run += v;
    }

    uint32_t inc = warp_incl_scan(run, lane);
    if (lane == 31) s_wsum[warp] = inc;
    __syncthreads();
    if (t == 0) {
        uint32_t acc = 0;
#pragma unroll
        for (int w = 0; w < 8; w++) { uint32_t x = s_wsum[w]; s_wsum[w] = acc; acc += x; }
    }
    __syncthreads();

    uint32_t excl = inc - run + s_wsum[warp] + s_base;
#pragma unroll 8
    for (int k = 0; k < VB; k++)
        row[t * VB + k] = el[k] + excl;
}

// ---------------------------------------------------------------------------
// K3: stable scatter. Block radix-rank + smem overlay. Byte-packed ids,
// SIMD ranks, uint2 (val,meta) staging -> low regs, fewer L1 instructions.
// ---------------------------------------------------------------------------
__global__ __launch_bounds__(BLOCK) void k_scatter(
    const float* __restrict__ scores,
    const int*   __restrict__ experts,
    float* __restrict__ out_scores,
    float* __restrict__ out_idx,
    int B)
{
    __shared__ uint32_t s_buf[2 * CHUNK];   // 32 KB overlay (hist | pairs)
    __shared__ int      s_delta[E];
    __shared__ uint32_t s_lbase[E];

    uint16_t* hist   = (uint16_t*)s_buf;    // [E][BLOCK] counts -> excl prefix
    uint2*    s_pair = (uint2*)s_buf;       // [CHUNK] (val_bits, meta)

    const int t = threadIdx.x;
    const int b = blockIdx.x;
    const int lane = t & 31, warp = t >> 5;

    // Reset g_totals for the next graph replay (k_scan already consumed it).
    if (b == 0 && t < E) g_totals[t] = 0u;

    // Byte-pack 16 expert ids (4 x LDG.128, coalesced).
    uint32_t epk[4];
    {
        const int4* ep = (const int4*)(experts + (size_t)b * CHUNK + t * ITEMS);
#pragma unroll
        for (int v = 0; v < 4; v++) {
            int4 x = ep[v];
            epk[v] = (uint32_t)x.x | ((uint32_t)x.y << 8) |
                     ((uint32_t)x.z << 16) | ((uint32_t)x.w << 24);
        }
    }

    // Zero hist (8 x STS.128).
    uint4 z4 = make_uint4(0u, 0u, 0u, 0u);
#pragma unroll
    for (int i = 0; i < 8; i++) ((uint4*)s_buf)[i * BLOCK + t] = z4;
    __syncthreads();

    // In-thread stable rank via SIMD byte compare; nibble-packed ranks.
    uint32_t rn0 = 0, rn1 = 0;
#pragma unroll
    for (int i = 0; i < ITEMS; i++) {
        const int qw = i >> 2, k = i & 3;
        uint32_t w  = epk[qw];
        uint32_t ei = (w >> (8 * k)) & 0xFFu;
        uint32_t bc = ei * 0x01010101u;
        uint32_t r  = __popc(__vcmpeq4(w, bc) & ((1u << (8 * k)) - 1u));
#pragma unroll
        for (int q = 0; q < 4; q++)
            if (q < qw) r += __popc(__vcmpeq4(epk[q], bc));
        r >>= 3;
        if (i < 8) rn0 |= r << (4 * i);
        else       rn1 |= r << (4 * (i - 8));
        hist[ei * BLOCK + t] = (uint16_t)(r + 1);
    }
    __syncthreads();

    // Per-expert exclusive scan over 256 thread counts (8 experts/warp).
#pragma unroll
    for (int s = 0; s < E / 8; s++) {
        int ex = warp * (E / 8) + s;
        uint4 v = ((const uint4*)(hist + ex * BLOCK))[lane];   // 8 u16
        uint32_t w[4] = { v.x, v.y, v.z, v.w };
        uint32_t run = 0, el[8];
#pragma unroll
        for (int k = 0; k < 8; k++) {
            uint32_t c = (w[k >> 1] >> ((k & 1) * 16)) & 0xFFFFu;
            el[k] = run; run += c;
        }
        uint32_t inc = warp_incl_scan(run, lane);
        uint32_t excl = inc - run;
#pragma unroll
        for (int k = 0; k < 8; k++) el[k] += excl;
        uint4 o;
        o.x = el[0] | (el[1] << 16);
        o.y = el[2] | (el[3] << 16);
        o.z = el[4] | (el[5] << 16);
        o.w = el[6] | (el[7] << 16);
        ((uint4*)(hist + ex * BLOCK))[lane] = o;
        if (lane == 31) s_lbase[ex] = inc;   // row total (temp)
    }
    __syncthreads();

    // Warp 0: block-local expert bases + delta vs scanned global offsets.
    if (warp == 0) {
        uint32_t t0 = s_lbase[lane];
        uint32_t t1 = s_lbase[lane + 32];
        uint32_t i0 = warp_incl_scan(t0, lane);
        uint32_t tot0 = __shfl_sync(0xffffffffu, i0, 31);
        uint32_t e0 = i0 - t0;
        uint32_t i1 = warp_incl_scan(t1, lane);
        uint32_t e1 = i1 - t1 + tot0;
        uint32_t gb0 = g_counts[(size_t)lane * B + b];
        uint32_t gb1 = g_counts[(size_t)(lane + 32) * B + b];
        s_lbase[lane]       = e0;
        s_lbase[lane + 32]  = e1;
        s_delta[lane]       = (int)gb0 - (int)e0;
        s_delta[lane + 32]  = (int)gb1 - (int)e1;
    }
    __syncthreads();

    // Per-item local positions into registers (u16-packed).
    uint32_t p16[ITEMS / 2];
#pragma unroll
    for (int i = 0; i < ITEMS; i++) {
        uint32_t ei = (epk[i >> 2] >> (8 * (i & 3))) & 0xFFu;
        uint32_t r  = (i < 8) ? ((rn0 >> (4 * i)) & 0xFu)
                              : ((rn1 >> (4 * (i - 8))) & 0xFu);
        uint32_t p = s_lbase[ei] + (uint32_t)hist[ei * BLOCK + t] + r;
        if (i & 1) p16[i >> 1] |= p << 16;
        else       p16[i >> 1]  = p;
    }
    __syncthreads();   // all hist reads done -> safe to overlay

    // Stage (val, meta) pairs into sorted order (scores loaded coalesced).
    {
        const float4* sp = (const float4*)(scores + (size_t)b * CHUNK + t * ITEMS);
#pragma unroll
        for (int v = 0; v < 4; v++) {
            float4 x = sp[v];
            float vv[4] = { x.x, x.y, x.z, x.w };
#pragma unroll
            for (int j = 0; j < 4; j++) {
                int i = 4 * v + j;
                uint32_t ei = (epk[v] >> (8 * j)) & 0xFFu;
                uint32_t p  = (p16[i >> 1] >> ((i & 1) * 16)) & 0xFFFFu;
                s_pair[p] = make_uint2(__float_as_uint(vv[j]),
                                       (uint32_t)(t * ITEMS + i) | (ei << 12));
            }
        }
    }
    __syncthreads();

    // Coalesced emit.
    const int chunk_base = b * CHUNK;
#pragma unroll
    for (int i = 0; i < ITEMS; i++) {
        int p = t + i * BLOCK;
        uint2 q = s_pair[p];
        int li = (int)(q.y & 0xFFFu);
        int ei = (int)(q.y >> 12);
        int gp = p + s_delta[ei];
        out_scores[gp] = __uint_as_float(q.x);
        out_idx[gp]    = (float)(chunk_base + li);
    }
}

// ---------------------------------------------------------------------------
extern "C" void kernel_launch(void* const* d_in, const int* in_sizes, int n_in,
                              void* d_out, int out_size) {
    const float* scores  = (const float*)d_in[0];
    const int*   experts = (const int*)d_in[1];
    const int N = in_sizes[0];            // 8,388,608
    const int B = N / CHUNK;              // 2048

    float* out        = (float*)d_out;
    float* out_scores = out;
    float* out_idx    = out + N;
    float* out_counts = out + 2 * (size_t)N;

    k_hist<<<B, BLOCK>>>(experts, B);
    k_scan<<<E, 256>>>(B, out_counts);
    k_scatter<<<B, BLOCK>>>(scores, experts, out_scores, out_idx, B);
}

// round 14
// speedup vs baseline: 1.0227x; 1.0036x over previous
#include <cuda_runtime.h>
#include <cuda_bf16.h>
#include <stdint.h>

#define E       64
#define BLOCK   256
#define ITEMS   16
#define CHUNK   (BLOCK * ITEMS)   // 4096

// Scratch (no allocation allowed): supports up to B = 4096 blocks / N = 16M.
__device__ uint32_t g_counts[E * 4096];
__device__ uint32_t g_totals[E];          // zero-init; re-zeroed by k_scatter b==0
__device__ uint32_t g_epk[4 * 1048576];   // byte-packed expert ids (16 MB cap)

__device__ __forceinline__ uint32_t warp_incl_scan(uint32_t x, int lane) {
#pragma unroll
    for (int o = 1; o < 32; o <<= 1) {
        uint32_t y = __shfl_up_sync(0xffffffffu, x, o);
        if (lane >= o) x += y;
    }
    return x;
}

// ---------------------------------------------------------------------------
// K1: per-(expert, block) histogram, expert-major: g_counts[e*B + b].
// Plain shared atomics (proven fastest). Also emits byte-packed expert ids.
// ---------------------------------------------------------------------------
__global__ __launch_bounds__(BLOCK) void k_hist(const int* __restrict__ experts, int B) {
    __shared__ uint32_t h[E];
    const int t = threadIdx.x;
    const int b = blockIdx.x;
    if (t < E) h[t] = 0u;
    __syncthreads();

    const int4* p = (const int4*)(experts + (size_t)b * CHUNK);
    uint32_t* pk_out = g_epk + (size_t)b * (CHUNK / 4);
#pragma unroll
    for (int i = 0; i < CHUNK / (4 * BLOCK); i++) {     // 4 iterations
        int4 x = p[i * BLOCK + t];
        atomicAdd(&h[x.x], 1u);
        atomicAdd(&h[x.y], 1u);
        atomicAdd(&h[x.z], 1u);
        atomicAdd(&h[x.w], 1u);
        pk_out[i * BLOCK + t] = (uint32_t)x.x | ((uint32_t)x.y << 8) |
                                ((uint32_t)x.z << 16) | ((uint32_t)x.w << 24);
    }
    __syncthreads();

    if (t < E) {
        uint32_t c = h[t];
        g_counts[(size_t)t * B + b] = c;
        atomicAdd(&g_totals[t], c);
    }
}

// ---------------------------------------------------------------------------
// K2: one block per expert. Seeds with exclusive scan of expert totals, then
// scans this expert's B per-block counts in place -> global start offsets.
// Also writes num_tokens_per_expert (float).
// ---------------------------------------------------------------------------
__global__ __launch_bounds__(256) void k_scan(int B, float* __restrict__ out_counts) {
    __shared__ uint32_t s_wsum[8];
    __shared__ uint32_t s_base;

    const int e = blockIdx.x;
    const int t = threadIdx.x;
    const int lane = t & 31, warp = t >> 5;

    if (t < 32) {
        uint32_t a = g_totals[t];
        uint32_t c = g_totals[t + 32];
        uint32_t contrib = (t < e ? a : 0u) + ((t + 32) < e ? c : 0u);
#pragma unroll
        for (int o = 16; o > 0; o >>= 1)
            contrib += __shfl_down_sync(0xffffffffu, contrib, o);
        if (t == 0) s_base = contrib;
    }
    if (t == 0) out_counts[e] = (float)g_totals[e];

    uint32_t* row = g_counts + (size_t)e * B;
    const int VB = B >> 8;               // 8 for B=2048
    uint32_t run = 0;
    uint32_t el[16];
#pragma unroll 8
    for (int k = 0; k < VB; k++) {
        uint32_t v = row[t * VB + k];
        el[k] = run;
        run += v;
    }

    uint32_t inc = warp_incl_scan(run, lane);
    if (lane == 31) s_wsum[warp] = inc;
    __syncthreads();
    if (t == 0) {
        uint32_t acc = 0;
#pragma unroll
        for (int w = 0; w < 8; w++) { uint32_t x = s_wsum[w]; s_wsum[w] = acc; acc += x; }
    }
    __syncthreads();

    uint32_t excl = inc - run + s_wsum[warp] + s_base;
#pragma unroll 8
    for (int k = 0; k < VB; k++)
        row[t * VB + k] = el[k] + excl;
}

// ---------------------------------------------------------------------------
// K3: stable scatter. Block radix-rank + smem overlay. Expert ids come
// pre-packed from g_epk (1 LDG.128, mostly L2-hit). uint2 staging; emit
// reads pairs two-at-a-time via LDS.128 (conflict-free).
// ---------------------------------------------------------------------------
__global__ __launch_bounds__(BLOCK) void k_scatter(
    const float* __restrict__ scores,
    float* __restrict__ out_scores,
    float* __restrict__ out_idx,
    int B)
{
    __shared__ uint32_t s_buf[2 * CHUNK];   // 32 KB overlay (hist | pairs)
    __shared__ int      s_delta[E];
    __shared__ uint32_t s_lbase[E];

    uint16_t* hist   = (uint16_t*)s_buf;    // [E][BLOCK] counts -> excl prefix
    uint2*    s_pair = (uint2*)s_buf;       // [CHUNK] (val_bits, meta)

    const int t = threadIdx.x;
    const int b = blockIdx.x;
    const int lane = t & 31, warp = t >> 5;

    // Reset g_totals for the next graph replay (k_scan already consumed it).
    if (b == 0 && t < E) g_totals[t] = 0u;

    // Packed expert ids: one LDG.128 (items 16t .. 16t+15).
    uint32_t epk[4];
    {
        uint4 x = ((const uint4*)(g_epk + (size_t)b * (CHUNK / 4)))[t];
        epk[0] = x.x; epk[1] = x.y; epk[2] = x.z; epk[3] = x.w;
    }

    // Zero hist (8 x STS.128).
    uint4 z4 = make_uint4(0u, 0u, 0u, 0u);
#pragma unroll
    for (int i = 0; i < 8; i++) ((uint4*)s_buf)[i * BLOCK + t] = z4;
    __syncthreads();

    // In-thread stable rank via SIMD byte compare; nibble-packed ranks.
    uint32_t rn0 = 0, rn1 = 0;
#pragma unroll
    for (int i = 0; i < ITEMS; i++) {
        const int qw = i >> 2, k = i & 3;
        uint32_t w  = epk[qw];
        uint32_t ei = (w >> (8 * k)) & 0xFFu;
        uint32_t bc = ei * 0x01010101u;
        uint32_t r  = __popc(__vcmpeq4(w, bc) & ((1u << (8 * k)) - 1u));
#pragma unroll
        for (int q = 0; q < 4; q++)
            if (q < qw) r += __popc(__vcmpeq4(epk[q], bc));
        r >>= 3;
        if (i < 8) rn0 |= r << (4 * i);
        else       rn1 |= r << (4 * (i - 8));
        hist[ei * BLOCK + t] = (uint16_t)(r + 1);
    }
    __syncthreads();

    // Per-expert exclusive scan over 256 thread counts (8 experts/warp).
#pragma unroll
    for (int s = 0; s < E / 8; s++) {
        int ex = warp * (E / 8) + s;
        uint4 v = ((const uint4*)(hist + ex * BLOCK))[lane];   // 8 u16
        uint32_t w[4] = { v.x, v.y, v.z, v.w };
        uint32_t run = 0, el[8];
#pragma unroll
        for (int k = 0; k < 8; k++) {
            uint32_t c = (w[k >> 1] >> ((k & 1) * 16)) & 0xFFFFu;
            el[k] = run; run += c;
        }
        uint32_t inc = warp_incl_scan(run, lane);
        uint32_t excl = inc - run;
#pragma unroll
        for (int k = 0; k < 8; k++) el[k] += excl;
        uint4 o;
        o.x = el[0] | (el[1] << 16);
        o.y = el[2] | (el[3] << 16);
        o.z = el[4] | (el[5] << 16);
        o.w = el[6] | (el[7] << 16);
        ((uint4*)(hist + ex * BLOCK))[lane] = o;
        if (lane == 31) s_lbase[ex] = inc;   // row total (temp)
    }
    __syncthreads();

    // Warp 0: block-local expert bases + delta vs scanned global offsets.
    if (warp == 0) {
        uint32_t t0 = s_lbase[lane];
        uint32_t t1 = s_lbase[lane + 32];
        uint32_t i0 = warp_incl_scan(t0, lane);
        uint32_t tot0 = __shfl_sync(0xffffffffu, i0, 31);
        uint32_t e0 = i0 - t0;
        uint32_t i1 = warp_incl_scan(t1, lane);
        uint32_t e1 = i1 - t1 + tot0;
        uint32_t gb0 = g_counts[(size_t)lane * B + b];
        uint32_t gb1 = g_counts[(size_t)(lane + 32) * B + b];
        s_lbase[lane]       = e0;
        s_lbase[lane + 32]  = e1;
        s_delta[lane]       = (int)gb0 - (int)e0;
        s_delta[lane + 32]  = (int)gb1 - (int)e1;
    }
    __syncthreads();

    // Per-item local positions into registers (u16-packed).
    uint32_t p16[ITEMS / 2];
#pragma unroll
    for (int i = 0; i < ITEMS; i++) {
        uint32_t ei = (epk[i >> 2] >> (8 * (i & 3))) & 0xFFu;
        uint32_t r  = (i < 8) ? ((rn0 >> (4 * i)) & 0xFu)
                              : ((rn1 >> (4 * (i - 8))) & 0xFu);
        uint32_t p = s_lbase[ei] + (uint32_t)hist[ei * BLOCK + t] + r;
        if (i & 1) p16[i >> 1] |= p << 16;
        else       p16[i >> 1]  = p;
    }
    __syncthreads();   // all hist reads done -> safe to overlay

    // Stage (val, meta) pairs into sorted order (scores loaded coalesced).
    {
        const float4* sp = (const float4*)(scores + (size_t)b * CHUNK + t * ITEMS);
#pragma unroll
        for (int v = 0; v < 4; v++) {
            float4 x = sp[v];
            float vv[4] = { x.x, x.y, x.z, x.w };
#pragma unroll
            for (int j = 0; j < 4; j++) {
                int i = 4 * v + j;
                uint32_t ei = (epk[v] >> (8 * j)) & 0xFFu;
                uint32_t p  = (p16[i >> 1] >> ((i & 1) * 16)) & 0xFFFFu;
                s_pair[p] = make_uint2(__float_as_uint(vv[j]),
                                       (uint32_t)(t * ITEMS + i) | (ei << 12));
            }
        }
    }
    __syncthreads();

    // Emit: two pairs per LDS.128 (conflict-free); scalar STG.32 outputs.
    const int chunk_base = b * CHUNK;
    const uint4* pairs4 = (const uint4*)s_pair;   // 2048 x uint4
#pragma unroll
    for (int it = 0; it < 8; it++) {
        int j = it * BLOCK + t;          // uint4 index
        uint4 q = pairs4[j];
        int p0 = 2 * j;
        int gp0 = p0     + s_delta[q.y >> 12];
        int gp1 = p0 + 1 + s_delta[q.w >> 12];
        out_scores[gp0] = __uint_as_float(q.x);
        out_scores[gp1] = __uint_as_float(q.z);
        out_idx[gp0]    = (float)(chunk_base + (int)(q.y & 0xFFFu));
        out_idx[gp1]    = (float)(chunk_base + (int)(q.w & 0xFFFu));
    }
}

// ---------------------------------------------------------------------------
extern "C" void kernel_launch(void* const* d_in, const int* in_sizes, int n_in,
                              void* d_out, int out_size) {
    const float* scores  = (const float*)d_in[0];
    const int*   experts = (const int*)d_in[1];
    const int N = in_sizes[0];            // 8,388,608
    const int B = N / CHUNK;              // 2048

    float* out        = (float*)d_out;
    float* out_scores = out;
    float* out_idx    = out + N;
    float* out_counts = out + 2 * (size_t)N;

    k_hist<<<B, BLOCK>>>(experts, B);
    k_scan<<<E, 256>>>(B, out_counts);
    k_scatter<<<B, BLOCK>>>(scores, out_scores, out_idx, B);
}

// round 15
// speedup vs baseline: 1.1024x; 1.0780x over previous
#include <cuda_runtime.h>
#include <cuda_bf16.h>
#include <stdint.h>

#define E        64
#define BLOCK    256
#define ITEMS    16
#define CHUNK    (BLOCK * ITEMS)   // 4096  (k_scan / k_scatter granularity)
#define CHUNK_H  (2 * CHUNK)       // 8192  (k_hist tile = two chunks)

// Scratch (no allocation allowed): supports up to B = 4096 chunks / N = 16M.
__device__ uint32_t g_counts[E * 4096];
__device__ uint32_t g_totals[E];          // zero-init; re-zeroed by k_scatter b==0
__device__ uint32_t g_epk[4 * 1048576];   // byte-packed expert ids (16 MB cap)

__device__ __forceinline__ uint32_t warp_incl_scan(uint32_t x, int lane) {
#pragma unroll
    for (int o = 1; o < 32; o <<= 1) {
        uint32_t y = __shfl_up_sync(0xffffffffu, x, o);
        if (lane >= o) x += y;
    }
    return x;
}

// ---------------------------------------------------------------------------
// K1: per-(expert, chunk) histogram over an 8192-element tile (2 chunks).
// Warps 0-3 count the first 4096 chunk into h[0], warps 4-7 the second into
// h[1] (striped loads: iterations 0-3 cover words 0-1023 = chunk 0).
// Also emits byte-packed expert ids for k_scatter.
// ---------------------------------------------------------------------------
__global__ __launch_bounds__(BLOCK) void k_hist(const int* __restrict__ experts, int B) {
    __shared__ uint32_t h[2][E];
    const int t = threadIdx.x;
    const int b = blockIdx.x;
    if (t < 2 * E) ((uint32_t*)h)[t] = 0u;
    __syncthreads();

    const int4* p = (const int4*)(experts + (size_t)b * CHUNK_H);
    uint32_t* pk_out = g_epk + (size_t)b * (CHUNK_H / 4);
#pragma unroll
    for (int i = 0; i < 8; i++) {                 // striped: word = i*256 + t
        int4 x = p[i * BLOCK + t];
        uint32_t* hh = h[i >> 2];                 // i<4 -> chunk 0, else chunk 1
        atomicAdd(&hh[x.x], 1u);
        atomicAdd(&hh[x.y], 1u);
        atomicAdd(&hh[x.z], 1u);
        atomicAdd(&hh[x.w], 1u);
        pk_out[i * BLOCK + t] = (uint32_t)x.x | ((uint32_t)x.y << 8) |
                                ((uint32_t)x.z << 16) | ((uint32_t)x.w << 24);
    }
    __syncthreads();

    if (t < E) {
        uint32_t c0 = h[0][t], c1 = h[1][t];
        g_counts[(size_t)t * B + 2 * b]     = c0;
        g_counts[(size_t)t * B + 2 * b + 1] = c1;
        atomicAdd(&g_totals[t], c0 + c1);
    }
}

// ---------------------------------------------------------------------------
// K2: one block per expert. Seeds with exclusive scan of expert totals, then
// scans this expert's B per-chunk counts in place -> global start offsets.
// Also writes num_tokens_per_expert (float).
// ---------------------------------------------------------------------------
__global__ __launch_bounds__(256) void k_scan(int B, float* __restrict__ out_counts) {
    __shared__ uint32_t s_wsum[8];
    __shared__ uint32_t s_base;

    const int e = blockIdx.x;
    const int t = threadIdx.x;
    const int lane = t & 31, warp = t >> 5;

    if (t < 32) {
        uint32_t a = g_totals[t];
        uint32_t c = g_totals[t + 32];
        uint32_t contrib = (t < e ? a : 0u) + ((t + 32) < e ? c : 0u);
#pragma unroll
        for (int o = 16; o > 0; o >>= 1)
            contrib += __shfl_down_sync(0xffffffffu, contrib, o);
        if (t == 0) s_base = contrib;
    }
    if (t == 0) out_counts[e] = (float)g_totals[e];

    uint32_t* row = g_counts + (size_t)e * B;
    const int VB = B >> 8;               // 8 for B=2048
    uint32_t run = 0;
    uint32_t el[16];
#pragma unroll 8
    for (int k = 0; k < VB; k++) {
        uint32_t v = row[t * VB + k];
        el[k] = run;
        run += v;
    }

    uint32_t inc = warp_incl_scan(run, lane);
    if (lane == 31) s_wsum[warp] = inc;
    __syncthreads();
    if (t == 0) {
        uint32_t acc = 0;
#pragma unroll
        for (int w = 0; w < 8; w++) { uint32_t x = s_wsum[w]; s_wsum[w] = acc; acc += x; }
    }
    __syncthreads();

    uint32_t excl = inc - run + s_wsum[warp] + s_base;
#pragma unroll 8
    for (int k = 0; k < VB; k++)
        row[t * VB + k] = el[k] + excl;
}

// ---------------------------------------------------------------------------
// K3: stable scatter. Block radix-rank + smem overlay. Expert ids come
// pre-packed from g_epk (1 LDG.128, mostly L2-hit). uint2 staging; emit
// reads pairs two-at-a-time via LDS.128 (conflict-free).
// min-blocks 5 -> target 51 regs, 5 blocks/SM (165 KB smem of 228 KB).
// ---------------------------------------------------------------------------
__global__ __launch_bounds__(BLOCK, 5) void k_scatter(
    const float* __restrict__ scores,
    float* __restrict__ out_scores,
    float* __restrict__ out_idx,
    int B)
{
    __shared__ uint32_t s_buf[2 * CHUNK];   // 32 KB overlay (hist | pairs)
    __shared__ int      s_delta[E];
    __shared__ uint32_t s_lbase[E];

    uint16_t* hist   = (uint16_t*)s_buf;    // [E][BLOCK] counts -> excl prefix
    uint2*    s_pair = (uint2*)s_buf;       // [CHUNK] (val_bits, meta)

    const int t = threadIdx.x;
    const int b = blockIdx.x;
    const int lane = t & 31, warp = t >> 5;

    // Reset g_totals for the next graph replay (k_scan already consumed it).
    if (b == 0 && t < E) g_totals[t] = 0u;

    // Packed expert ids: one LDG.128 (items 16t .. 16t+15).
    uint32_t epk[4];
    {
        uint4 x = ((const uint4*)(g_epk + (size_t)b * (CHUNK / 4)))[t];
        epk[0] = x.x; epk[1] = x.y; epk[2] = x.z; epk[3] = x.w;
    }

    // Zero hist (8 x STS.128).
    uint4 z4 = make_uint4(0u, 0u, 0u, 0u);
#pragma unroll
    for (int i = 0; i < 8; i++) ((uint4*)s_buf)[i * BLOCK + t] = z4;
    __syncthreads();

    // In-thread stable rank via SIMD byte compare; nibble-packed ranks.
    uint32_t rn0 = 0, rn1 = 0;
#pragma unroll
    for (int i = 0; i < ITEMS; i++) {
        const int qw = i >> 2, k = i & 3;
        uint32_t w  = epk[qw];
        uint32_t ei = (w >> (8 * k)) & 0xFFu;
        uint32_t bc = ei * 0x01010101u;
        uint32_t r  = __popc(__vcmpeq4(w, bc) & ((1u << (8 * k)) - 1u));
#pragma unroll
        for (int q = 0; q < 4; q++)
            if (q < qw) r += __popc(__vcmpeq4(epk[q], bc));
        r >>= 3;
        if (i < 8) rn0 |= r << (4 * i);
        else       rn1 |= r << (4 * (i - 8));
        hist[ei * BLOCK + t] = (uint16_t)(r + 1);
    }
    __syncthreads();

    // Per-expert exclusive scan over 256 thread counts (8 experts/warp).
#pragma unroll
    for (int s = 0; s < E / 8; s++) {
        int ex = warp * (E / 8) + s;
        uint4 v = ((const uint4*)(hist + ex * BLOCK))[lane];   // 8 u16
        uint32_t w[4] = { v.x, v.y, v.z, v.w };
        uint32_t run = 0, el[8];
#pragma unroll
        for (int k = 0; k < 8; k++) {
            uint32_t c = (w[k >> 1] >> ((k & 1) * 16)) & 0xFFFFu;
            el[k] = run; run += c;
        }
        uint32_t inc = warp_incl_scan(run, lane);
        uint32_t excl = inc - run;
#pragma unroll
        for (int k = 0; k < 8; k++) el[k] += excl;
        uint4 o;
        o.x = el[0] | (el[1] << 16);
        o.y = el[2] | (el[3] << 16);
        o.z = el[4] | (el[5] << 16);
        o.w = el[6] | (el[7] << 16);
        ((uint4*)(hist + ex * BLOCK))[lane] = o;
        if (lane == 31) s_lbase[ex] = inc;   // row total (temp)
    }
    __syncthreads();

    // Warp 0: block-local expert bases + delta vs scanned global offsets.
    if (warp == 0) {
        uint32_t t0 = s_lbase[lane];
        uint32_t t1 = s_lbase[lane + 32];
        uint32_t i0 = warp_incl_scan(t0, lane);
        uint32_t tot0 = __shfl_sync(0xffffffffu, i0, 31);
        uint32_t e0 = i0 - t0;
        uint32_t i1 = warp_incl_scan(t1, lane);
        uint32_t e1 = i1 - t1 + tot0;
        uint32_t gb0 = g_counts[(size_t)lane * B + b];
        uint32_t gb1 = g_counts[(size_t)(lane + 32) * B + b];
        s_lbase[lane]       = e0;
        s_lbase[lane + 32]  = e1;
        s_delta[lane]       = (int)gb0 - (int)e0;
        s_delta[lane + 32]  = (int)gb1 - (int)e1;
    }
    __syncthreads();

    // Per-item local positions into registers (u16-packed).
    uint32_t p16[ITEMS / 2];
#pragma unroll
    for (int i = 0; i < ITEMS; i++) {
        uint32_t ei = (epk[i >> 2] >> (8 * (i & 3))) & 0xFFu;
        uint32_t r  = (i < 8) ? ((rn0 >> (4 * i)) & 0xFu)
                              : ((rn1 >> (4 * (i - 8))) & 0xFu);
        uint32_t p = s_lbase[ei] + (uint32_t)hist[ei * BLOCK + t] + r;
        if (i & 1) p16[i >> 1] |= p << 16;
        else       p16[i >> 1]  = p;
    }
    __syncthreads();   // all hist reads done -> safe to overlay

    // Stage (val, meta) pairs into sorted order (scores loaded coalesced).
    {
        const float4* sp = (const float4*)(scores + (size_t)b * CHUNK + t * ITEMS);
#pragma unroll
        for (int v = 0; v < 4; v++) {
            float4 x = sp[v];
            float vv[4] = { x.x, x.y, x.z, x.w };
#pragma unroll
            for (int j = 0; j < 4; j++) {
                int i = 4 * v + j;
                uint32_t ei = (epk[v] >> (8 * j)) & 0xFFu;
                uint32_t p  = (p16[i >> 1] >> ((i & 1) * 16)) & 0xFFFFu;
                s_pair[p] = make_uint2(__float_as_uint(vv[j]),
                                       (uint32_t)(t * ITEMS + i) | (ei << 12));
            }
        }
    }
    __syncthreads();

    // Emit: two pairs per LDS.128 (conflict-free); scalar STG.32 outputs.
    const int chunk_base = b * CHUNK;
    const uint4* pairs4 = (const uint4*)s_pair;   // 2048 x uint4
#pragma unroll
    for (int it = 0; it < 8; it++) {
        int j = it * BLOCK + t;          // uint4 index
        uint4 q = pairs4[j];
        int p0 = 2 * j;
        int gp0 = p0     + s_delta[q.y >> 12];
        int gp1 = p0 + 1 + s_delta[q.w >> 12];
        out_scores[gp0] = __uint_as_float(q.x);
        out_scores[gp1] = __uint_as_float(q.z);
        out_idx[gp0]    = (float)(chunk_base + (int)(q.y & 0xFFFu));
        out_idx[gp1]    = (float)(chunk_base + (int)(q.w & 0xFFFu));
    }
}

// ---------------------------------------------------------------------------
extern "C" void kernel_launch(void* const* d_in, const int* in_sizes, int n_in,
                              void* d_out, int out_size) {
    const float* scores  = (const float*)d_in[0];
    const int*   experts = (const int*)d_in[1];
    const int N = in_sizes[0];            // 8,388,608
    const int B = N / CHUNK;              // 2048 chunks of 4096

    float* out        = (float*)d_out;
    float* out_scores = out;
    float* out_idx    = out + N;
    float* out_counts = out + 2 * (size_t)N;

    k_hist<<<B / 2, BLOCK>>>(experts, B);     // 1024 blocks, 8192/tile
    k_scan<<<E, 256>>>(B, out_counts);
    k_scatter<<<B, BLOCK>>>(scores, out_scores, out_idx, B);
}

// round 16
// speedup vs baseline: 1.1360x; 1.0304x over previous
#include <cuda_runtime.h>
#include <cuda_bf16.h>
#include <stdint.h>

#define E        64
#define BLOCK    256
#define ITEMS    16
#define CHUNK    (BLOCK * ITEMS)   // 4096  (k_scan / k_scatter granularity)
#define CHUNK_H  (4 * CHUNK)       // 16384 (k_hist tile = four chunks)

// Scratch (no allocation allowed): supports up to B = 4096 chunks / N = 16M.
__device__ uint32_t g_counts[E * 4096];
__device__ uint32_t g_totals[E];          // zero-init; re-zeroed by k_scatter b==0
__device__ uint32_t g_epk[4 * 1048576];   // byte-packed expert ids (16 MB cap)

__device__ __forceinline__ uint32_t warp_incl_scan(uint32_t x, int lane) {
#pragma unroll
    for (int o = 1; o < 32; o <<= 1) {
        uint32_t y = __shfl_up_sync(0xffffffffu, x, o);
        if (lane >= o) x += y;
    }
    return x;
}

// ---------------------------------------------------------------------------
// K1: per-(expert, chunk) histogram over a 16384-element tile (4 chunks).
// Striped loads: iterations 4j..4j+3 cover words of chunk j -> sub-hist h[j].
// Also emits byte-packed expert ids for k_scatter.
// ---------------------------------------------------------------------------
__global__ __launch_bounds__(BLOCK) void k_hist(const int* __restrict__ experts, int B) {
    __shared__ uint32_t h[4][E];
    const int t = threadIdx.x;
    const int b = blockIdx.x;
    if (t < 4 * E) ((uint32_t*)h)[t] = 0u;
    __syncthreads();

    const int4* p = (const int4*)(experts + (size_t)b * CHUNK_H);
    uint32_t* pk_out = g_epk + (size_t)b * (CHUNK_H / 4);
#pragma unroll
    for (int i = 0; i < 16; i++) {                // word = i*256 + t
        int4 x = p[i * BLOCK + t];
        uint32_t* hh = h[i >> 2];                 // chunk = i/4
        atomicAdd(&hh[x.x], 1u);
        atomicAdd(&hh[x.y], 1u);
        atomicAdd(&hh[x.z], 1u);
        atomicAdd(&hh[x.w], 1u);
        pk_out[i * BLOCK + t] = (uint32_t)x.x | ((uint32_t)x.y << 8) |
                                ((uint32_t)x.z << 16) | ((uint32_t)x.w << 24);
    }
    __syncthreads();

    if (t < E) {
        uint32_t c0 = h[0][t], c1 = h[1][t], c2 = h[2][t], c3 = h[3][t];
        g_counts[(size_t)t * B + 4 * b]     = c0;
        g_counts[(size_t)t * B + 4 * b + 1] = c1;
        g_counts[(size_t)t * B + 4 * b + 2] = c2;
        g_counts[(size_t)t * B + 4 * b + 3] = c3;
        atomicAdd(&g_totals[t], c0 + c1 + c2 + c3);
    }
}

// ---------------------------------------------------------------------------
// K2: one block per expert. Seeds with exclusive scan of expert totals, then
// scans this expert's B per-chunk counts in place -> global start offsets.
// Also writes num_tokens_per_expert (float).
// ---------------------------------------------------------------------------
__global__ __launch_bounds__(256) void k_scan(int B, float* __restrict__ out_counts) {
    __shared__ uint32_t s_wsum[8];
    __shared__ uint32_t s_base;

    const int e = blockIdx.x;
    const int t = threadIdx.x;
    const int lane = t & 31, warp = t >> 5;

    if (t < 32) {
        uint32_t a = g_totals[t];
        uint32_t c = g_totals[t + 32];
        uint32_t contrib = (t < e ? a : 0u) + ((t + 32) < e ? c : 0u);
#pragma unroll
        for (int o = 16; o > 0; o >>= 1)
            contrib += __shfl_down_sync(0xffffffffu, contrib, o);
        if (t == 0) s_base = contrib;
    }
    if (t == 0) out_counts[e] = (float)g_totals[e];

    uint32_t* row = g_counts + (size_t)e * B;
    const int VB = B >> 8;               // 8 for B=2048
    uint32_t run = 0;
    uint32_t el[16];
#pragma unroll 8
    for (int k = 0; k < VB; k++) {
        uint32_t v = row[t * VB + k];
        el[k] = run;
        run += v;
    }

    uint32_t inc = warp_incl_scan(run, lane);
    if (lane == 31) s_wsum[warp] = inc;
    __syncthreads();
    if (t == 0) {
        uint32_t acc = 0;
#pragma unroll
        for (int w = 0; w < 8; w++) { uint32_t x = s_wsum[w]; s_wsum[w] = acc; acc += x; }
    }
    __syncthreads();

    uint32_t excl = inc - run + s_wsum[warp] + s_base;
#pragma unroll 8
    for (int k = 0; k < VB; k++)
        row[t * VB + k] = el[k] + excl;
}

// ---------------------------------------------------------------------------
// K3: stable scatter. Block radix-rank + smem overlay. Score loads issued
// early (right after rank phase) so scan/readback hides their DRAM latency.
// ---------------------------------------------------------------------------
__global__ __launch_bounds__(BLOCK, 5) void k_scatter(
    const float* __restrict__ scores,
    float* __restrict__ out_scores,
    float* __restrict__ out_idx,
    int B)
{
    __shared__ uint32_t s_buf[2 * CHUNK];   // 32 KB overlay (hist | pairs)
    __shared__ int      s_delta[E];
    __shared__ uint32_t s_lbase[E];

    uint16_t* hist   = (uint16_t*)s_buf;    // [E][BLOCK] counts -> excl prefix
    uint2*    s_pair = (uint2*)s_buf;       // [CHUNK] (val_bits, meta)

    const int t = threadIdx.x;
    const int b = blockIdx.x;
    const int lane = t & 31, warp = t >> 5;

    // Reset g_totals for the next graph replay (k_scan already consumed it).
    if (b == 0 && t < E) g_totals[t] = 0u;

    // Packed expert ids: one LDG.128 (items 16t .. 16t+15).
    uint32_t epk[4];
    {
        uint4 x = ((const uint4*)(g_epk + (size_t)b * (CHUNK / 4)))[t];
        epk[0] = x.x; epk[1] = x.y; epk[2] = x.z; epk[3] = x.w;
    }

    // Zero hist (8 x STS.128).
    uint4 z4 = make_uint4(0u, 0u, 0u, 0u);
#pragma unroll
    for (int i = 0; i < 8; i++) ((uint4*)s_buf)[i * BLOCK + t] = z4;
    __syncthreads();

    // In-thread stable rank via SIMD byte compare; nibble-packed ranks.
    uint32_t rn0 = 0, rn1 = 0;
#pragma unroll
    for (int i = 0; i < ITEMS; i++) {
        const int qw = i >> 2, k = i & 3;
        uint32_t w  = epk[qw];
        uint32_t ei = (w >> (8 * k)) & 0xFFu;
        uint32_t bc = ei * 0x01010101u;
        uint32_t r  = __popc(__vcmpeq4(w, bc) & ((1u << (8 * k)) - 1u));
#pragma unroll
        for (int q = 0; q < 4; q++)
            if (q < qw) r += __popc(__vcmpeq4(epk[q], bc));
        r >>= 3;
        if (i < 8) rn0 |= r << (4 * i);
        else       rn1 |= r << (4 * (i - 8));
        hist[ei * BLOCK + t] = (uint16_t)(r + 1);
    }

    // Issue score loads NOW: their DRAM latency is hidden behind the
    // scan + base + readback phases below.
    float4 sv[4];
    {
        const float4* sp = (const float4*)(scores + (size_t)b * CHUNK + t * ITEMS);
        sv[0] = sp[0]; sv[1] = sp[1]; sv[2] = sp[2]; sv[3] = sp[3];
    }
    __syncthreads();

    // Per-expert exclusive scan over 256 thread counts (8 experts/warp).
#pragma unroll
    for (int s = 0; s < E / 8; s++) {
        int ex = warp * (E / 8) + s;
        uint4 v = ((const uint4*)(hist + ex * BLOCK))[lane];   // 8 u16
        uint32_t w[4] = { v.x, v.y, v.z, v.w };
        uint32_t run = 0, el[8];
#pragma unroll
        for (int k = 0; k < 8; k++) {
            uint32_t c = (w[k >> 1] >> ((k & 1) * 16)) & 0xFFFFu;
            el[k] = run; run += c;
        }
        uint32_t inc = warp_incl_scan(run, lane);
        uint32_t excl = inc - run;
#pragma unroll
        for (int k = 0; k < 8; k++) el[k] += excl;
        uint4 o;
        o.x = el[0] | (el[1] << 16);
        o.y = el[2] | (el[3] << 16);
        o.z = el[4] | (el[5] << 16);
        o.w = el[6] | (el[7] << 16);
        ((uint4*)(hist + ex * BLOCK))[lane] = o;
        if (lane == 31) s_lbase[ex] = inc;   // row total (temp)
    }
    __syncthreads();

    // Warp 0: block-local expert bases + delta vs scanned global offsets.
    if (warp == 0) {
        uint32_t t0 = s_lbase[lane];
        uint32_t t1 = s_lbase[lane + 32];
        uint32_t i0 = warp_incl_scan(t0, lane);
        uint32_t tot0 = __shfl_sync(0xffffffffu, i0, 31);
        uint32_t e0 = i0 - t0;
        uint32_t i1 = warp_incl_scan(t1, lane);
        uint32_t e1 = i1 - t1 + tot0;
        uint32_t gb0 = g_counts[(size_t)lane * B + b];
        uint32_t gb1 = g_counts[(size_t)(lane + 32) * B + b];
        s_lbase[lane]       = e0;
        s_lbase[lane + 32]  = e1;
        s_delta[lane]       = (int)gb0 - (int)e0;
        s_delta[lane + 32]  = (int)gb1 - (int)e1;
    }
    __syncthreads();

    // Per-item local positions into registers (u16-packed).
    uint32_t p16[ITEMS / 2];
#pragma unroll
    for (int i = 0; i < ITEMS; i++) {
        uint32_t ei = (epk[i >> 2] >> (8 * (i & 3))) & 0xFFu;
        uint32_t r  = (i < 8) ? ((rn0 >> (4 * i)) & 0xFu)
                              : ((rn1 >> (4 * (i - 8))) & 0xFu);
        uint32_t p = s_lbase[ei] + (uint32_t)hist[ei * BLOCK + t] + r;
        if (i & 1) p16[i >> 1] |= p << 16;
        else       p16[i >> 1]  = p;
    }
    __syncthreads();   // all hist reads done -> safe to overlay

    // Stage (val, meta) pairs into sorted order (scores already in registers).
    {
#pragma unroll
        for (int v = 0; v < 4; v++) {
            float vv[4] = { sv[v].x, sv[v].y, sv[v].z, sv[v].w };
#pragma unroll
            for (int j = 0; j < 4; j++) {
                int i = 4 * v + j;
                uint32_t ei = (epk[v] >> (8 * j)) & 0xFFu;
                uint32_t p  = (p16[i >> 1] >> ((i & 1) * 16)) & 0xFFFFu;
                s_pair[p] = make_uint2(__float_as_uint(vv[j]),
                                       (uint32_t)(t * ITEMS + i) | (ei << 12));
            }
        }
    }
    __syncthreads();

    // Emit: two pairs per LDS.128 (conflict-free); scalar STG.32 outputs.
    const int chunk_base = b * CHUNK;
    const uint4* pairs4 = (const uint4*)s_pair;   // 2048 x uint4
#pragma unroll
    for (int it = 0; it < 8; it++) {
        int j = it * BLOCK + t;          // uint4 index
        uint4 q = pairs4[j];
        int p0 = 2 * j;
        int gp0 = p0     + s_delta[q.y >> 12];
        int gp1 = p0 + 1 + s_delta[q.w >> 12];
        out_scores[gp0] = __uint_as_float(q.x);
        out_scores[gp1] = __uint_as_float(q.z);
        out_idx[gp0]    = (float)(chunk_base + (int)(q.y & 0xFFFu));
        out_idx[gp1]    = (float)(chunk_base + (int)(q.w & 0xFFFu));
    }
}

// ---------------------------------------------------------------------------
extern "C" void kernel_launch(void* const* d_in, const int* in_sizes, int n_in,
                              void* d_out, int out_size) {
    const float* scores  = (const float*)d_in[0];
    const int*   experts = (const int*)d_in[1];
    const int N = in_sizes[0];            // 8,388,608
    const int B = N / CHUNK;              // 2048 chunks of 4096

    float* out        = (float*)d_out;
    float* out_scores = out;
    float* out_idx    = out + N;
    float* out_counts = out + 2 * (size_t)N;

    k_hist<<<B / 4, BLOCK>>>(experts, B);     // 512 blocks, 16384/tile
    k_scan<<<E, 256>>>(B, out_counts);
    k_scatter<<<B, BLOCK>>>(scores, out_scores, out_idx, B);
}